// round 17
// baseline (speedup 1.0000x reference)
#include <cuda_runtime.h>
#include <cuda_fp16.h>
#include <cstdint>

// Problem constants (fixed by reference)
#define BATCH   4
#define NTOK    8192
#define DIM     768
#define SEGW    512
#define NSEG    16
#define MG      256       // gathered (even) rows per segment
#define TM      128       // Q rows per CTA tile
#define KC      64        // phase-1 k-dims per chunk (4 x k16 steps)
#define NCHUNK  12
#define THREADS 256

#define DCH     192       // phase-3 d chunk width
#define NIT3    16        // 4 d-chunks x 4 slabs (64 k-rows each)

// Strides in 32-bit words (1 word = half2). Lane-exact conflict-free:
// K: 36 w (ln4*36+lc4 mod 32 distinct); P: 132 w; V: 200 w.
#define KSW  36
#define PSW  132
#define VSW  200

#define KCHW   (MG*KSW)       // 9216 words per K ring slot (36864 B)
#define KRINGW 16896          // K ring start (word), after P region (67584 B)
#define V_OFFW 16896          // V ring aliases K ring region (phase 1 dead)
#define VSLABW (32*VSW)       // 6400 words per V slot
#define RED1W  44544          // redmax (after K ring: 16896+3*9216)
#define RED2W  45056          // redsum
#define SMEM_BYTES 182272     // 45568 words

#define SCHED_FENCE() asm volatile("" ::: "memory")

__device__ __forceinline__ uint32_t h2u(float a, float b) {
    __half2 h = __floats2half2_rn(a, b);
    return *reinterpret_cast<uint32_t*>(&h);
}
__device__ __forceinline__ uint4 pack8(float4 lo, float4 hi) {
    return make_uint4(h2u(lo.x, lo.y), h2u(lo.z, lo.w),
                      h2u(hi.x, hi.y), h2u(hi.z, hi.w));
}

__device__ __forceinline__ void mma16(float c[4], const uint32_t a[4], const uint32_t b[2]) {
    asm volatile(
        "mma.sync.aligned.m16n8k16.row.col.f32.f16.f16.f32 "
        "{%0,%1,%2,%3}, {%4,%5,%6,%7}, {%8,%9}, {%0,%1,%2,%3};\n"
        : "+f"(c[0]), "+f"(c[1]), "+f"(c[2]), "+f"(c[3])
        : "r"(a[0]), "r"(a[1]), "r"(a[2]), "r"(a[3]), "r"(b[0]), "r"(b[1]));
}

__global__ __launch_bounds__(THREADS, 1)
void dilated_attn_kernel(const float* __restrict__ x, float* __restrict__ y)
{
    extern __shared__ float sm[];
    uint32_t* smu = (uint32_t*)sm;
    const int tid  = threadIdx.x;
    const int lane = tid & 31;
    const int wid  = tid >> 5;     // 0..7

    const int mtile = blockIdx.x & 1;       // 2 x 128-row tiles per problem
    const int pid   = blockIdx.x >> 1;      // 64 problems
    const long segbase = (long)(pid >> 4) * NTOK + (long)(pid & 15) * SEGW;
    const int  m0 = mtile * TM;

    // Warp layout (both GEMMs): 2 m-warps x 4 n-warps, 64-row warp tiles
    const int wm  = wid & 1;
    const int wn  = wid >> 1;
    const int ln4 = lane >> 2;   // fragment group 0..7
    const int lc4 = lane & 3;    // thread-in-group 0..3

    const float* xrow = x + (size_t)(segbase + 2 * tid) * DIM;  // this thread's K fill row

    // ============ Phase 1: S = Q K^T (128 x 256 fp32 acc), KC=64, 3-slot ring ====
    float acc[4][8][4];
    #pragma unroll
    for (int mt = 0; mt < 4; mt++)
        #pragma unroll
        for (int nt = 0; nt < 8; nt++)
            #pragma unroll
            for (int i = 0; i < 4; i++)
                acc[mt][nt][i] = 0.f;

    // Prologue: chunks 0,1 filled directly (LDG -> cvt -> STS), slots 0,1
    #pragma unroll
    for (int c0 = 0; c0 < 2; c0++) {
        #pragma unroll
        for (int u = 0; u < 8; u++) {
            const float* src = xrow + c0 * KC + u * 8;
            float4 lo = *(const float4*)src;
            float4 hi = *(const float4*)(src + 4);
            *(uint4*)(smu + KRINGW + c0 * KCHW + tid * KSW + u * 4) = pack8(lo, hi);
        }
    }

    uint4 kstg[8];   // converted staging for chunk kc+2 (8 uint4 = this thread's row)
    for (int kc = 0; kc < NCHUNK; kc++) {
        __syncthreads();   // chunk kc visible; mma(kc-1) done by all
        const bool doSTS = (kc >= 1) && (kc + 1 < NCHUNK);
        const bool doLDG = (kc + 2 < NCHUNK);
        uint32_t* stsDst = smu + KRINGW + ((kc + 1) % 3) * KCHW + tid * KSW;
        const int kdN = (kc + 2) * KC;
        const uint32_t* cur = smu + KRINGW + (kc % 3) * KCHW;
        const uint32_t* abase = cur + (m0 + wm * 64 + ln4) * KSW + lc4;
        const uint32_t* bbase = cur + (wn * 64 + ln4) * KSW + lc4;

        uint32_t aF[2][4][4], bF[2][2];
        #pragma unroll
        for (int mt = 0; mt < 4; mt++) {
            const uint32_t* ba = abase + mt * 576;        // 16*KSW
            aF[0][mt][0] = ba[0];
            aF[0][mt][1] = ba[288];                       // 8*KSW
            aF[0][mt][2] = ba[4];
            aF[0][mt][3] = ba[292];
        }
        bF[0][0] = bbase[0];
        bF[0][1] = bbase[4];

        #pragma unroll
        for (int ks = 0; ks < 4; ks++) {
            const int cs = ks & 1;
            #pragma unroll
            for (int nt = 0; nt < 8; nt++) {
                const int cb = (ks * 8 + nt) & 1, nb = cb ^ 1;
                // next B fragment: (ks, nt+1) or (ks+1, 0)
                if (nt < 7) {
                    const uint32_t* bb = bbase + (nt + 1) * 288 + ks * 8;
                    bF[nb][0] = bb[0];
                    bF[nb][1] = bb[4];
                } else if (ks < 3) {
                    const uint32_t* bb = bbase + (ks + 1) * 8;
                    bF[nb][0] = bb[0];
                    bF[nb][1] = bb[4];
                }
                // next A fragments: one mt per group at nt<4
                if (ks < 3 && nt < 4) {
                    const int mt = nt;
                    const uint32_t* ba = abase + mt * 576 + (ks + 1) * 8;
                    aF[cs ^ 1][mt][0] = ba[0];
                    aF[cs ^ 1][mt][1] = ba[288];
                    aF[cs ^ 1][mt][2] = ba[4];
                    aF[cs ^ 1][mt][3] = ba[292];
                }
                // STS chunk kc+1 (from kstg): one uint4 per group at ks==0
                if (ks == 0 && doSTS) {
                    *(uint4*)(stsDst + nt * 4) = kstg[nt];
                }
                // LDG+cvt chunk kc+2: one 8-dim unit per group at ks==1
                if (ks == 1 && doLDG) {
                    const float* src = xrow + kdN + nt * 8;
                    float4 lo = *(const float4*)src;
                    float4 hi = *(const float4*)(src + 4);
                    kstg[nt] = pack8(lo, hi);
                }
                // odd-row zero stores: 8 per chunk at ks==2
                if (ks == 2) {
                    int i = (kc * 8 + nt) * THREADS + tid;   // 0..24575
                    int r = i / 192, c4 = i % 192;
                    long tok = segbase + 2 * (long)(m0 + r) + 1;
                    *(float4*)(y + (size_t)tok * DIM + c4 * 4) = make_float4(0.f, 0.f, 0.f, 0.f);
                }
                SCHED_FENCE();
                #pragma unroll
                for (int mt = 0; mt < 4; mt++)
                    mma16(acc[mt][nt], aF[cs][mt], bF[cb]);
                SCHED_FENCE();
            }
        }
    }

    // Prefetch phase-3 V tile 0 (STS deferred until after the barrier); lands under softmax.
    float4 vstg[12];
    #pragma unroll
    for (int j = 0; j < 6; j++) {
        int idx = j * THREADS + tid;
        int p = idx / 48, c4 = idx % 48;
        const float* s0 = x + (size_t)(segbase + 4 * p) * DIM + c4 * 4;
        vstg[2 * j]     = *(const float4*)s0;
        vstg[2 * j + 1] = *(const float4*)(s0 + 2 * DIM);
    }

    __syncthreads();   // all K-ring reads done (V ring aliases it)

    // ============ Phase 2: softmax in registers; P written once as half2 ============
    const float scale = 0.03608439182435161f;  // 768^-0.5
    #pragma unroll
    for (int mt = 0; mt < 4; mt++)
        #pragma unroll
        for (int nt = 0; nt < 8; nt++)
            #pragma unroll
            for (int i = 0; i < 4; i++)
                acc[mt][nt][i] *= scale;

    float* red1 = (float*)(smu + RED1W);
    float* red2 = (float*)(smu + RED2W);
    float mxv[8], inv[8];
    #pragma unroll
    for (int mt = 0; mt < 4; mt++) {
        float m0v = -1e30f, m1v = -1e30f;
        #pragma unroll
        for (int nt = 0; nt < 8; nt++) {
            m0v = fmaxf(m0v, fmaxf(acc[mt][nt][0], acc[mt][nt][1]));
            m1v = fmaxf(m1v, fmaxf(acc[mt][nt][2], acc[mt][nt][3]));
        }
        mxv[mt * 2]     = m0v;
        mxv[mt * 2 + 1] = m1v;
    }
    #pragma unroll
    for (int s = 0; s < 8; s++) {
        mxv[s] = fmaxf(mxv[s], __shfl_xor_sync(~0u, mxv[s], 1));
        mxv[s] = fmaxf(mxv[s], __shfl_xor_sync(~0u, mxv[s], 2));
    }
    if (lc4 == 0) {
        #pragma unroll
        for (int s = 0; s < 8; s++) {
            int row = wm * 64 + (s >> 1) * 16 + (s & 1) * 8 + ln4;
            red1[wn * 128 + row] = mxv[s];
        }
    }
    __syncthreads();
    #pragma unroll
    for (int s = 0; s < 8; s++) {
        int row = wm * 64 + (s >> 1) * 16 + (s & 1) * 8 + ln4;
        mxv[s] = fmaxf(fmaxf(red1[row], red1[128 + row]),
                       fmaxf(red1[256 + row], red1[384 + row]));
    }
    #pragma unroll
    for (int mt = 0; mt < 4; mt++) {
        float s0v = 0.f, s1v = 0.f;
        #pragma unroll
        for (int nt = 0; nt < 8; nt++) {
            acc[mt][nt][0] = __expf(acc[mt][nt][0] - mxv[mt * 2]);
            acc[mt][nt][1] = __expf(acc[mt][nt][1] - mxv[mt * 2]);
            acc[mt][nt][2] = __expf(acc[mt][nt][2] - mxv[mt * 2 + 1]);
            acc[mt][nt][3] = __expf(acc[mt][nt][3] - mxv[mt * 2 + 1]);
            s0v += acc[mt][nt][0] + acc[mt][nt][1];
            s1v += acc[mt][nt][2] + acc[mt][nt][3];
        }
        inv[mt * 2]     = s0v;
        inv[mt * 2 + 1] = s1v;
    }
    #pragma unroll
    for (int s = 0; s < 8; s++) {
        inv[s] += __shfl_xor_sync(~0u, inv[s], 1);
        inv[s] += __shfl_xor_sync(~0u, inv[s], 2);
    }
    if (lc4 == 0) {
        #pragma unroll
        for (int s = 0; s < 8; s++) {
            int row = wm * 64 + (s >> 1) * 16 + (s & 1) * 8 + ln4;
            red2[wn * 128 + row] = inv[s];
        }
    }
    __syncthreads();
    #pragma unroll
    for (int s = 0; s < 8; s++) {
        int row = wm * 64 + (s >> 1) * 16 + (s & 1) * 8 + ln4;
        inv[s] = 1.f / (red2[row] + red2[128 + row] + red2[256 + row] + red2[384 + row]);
    }
    // write P as half2 (row r, cols c,c+1)
    #pragma unroll
    for (int mt = 0; mt < 4; mt++)
        #pragma unroll
        for (int nt = 0; nt < 8; nt++) {
            int r0 = wm * 64 + mt * 16 + ln4;
            int cw = (wn * 64 + nt * 8 + 2 * lc4) >> 1;   // word column
            smu[r0 * PSW + cw]       = h2u(acc[mt][nt][0] * inv[mt * 2],
                                           acc[mt][nt][1] * inv[mt * 2]);
            smu[(r0 + 8) * PSW + cw] = h2u(acc[mt][nt][2] * inv[mt * 2 + 1],
                                           acc[mt][nt][3] * inv[mt * 2 + 1]);
        }

    // V tile 0 -> slot 0; direct-fill tile 1 -> slot 1
    #pragma unroll
    for (int j = 0; j < 6; j++) {
        int idx = j * THREADS + tid;
        int p = idx / 48, c4 = idx % 48;
        float4 lo = vstg[2 * j], hi = vstg[2 * j + 1];
        uint4 w = make_uint4(h2u(lo.x, hi.x), h2u(lo.y, hi.y),
                             h2u(lo.z, hi.z), h2u(lo.w, hi.w));
        *(uint4*)(smu + V_OFFW + p * VSW + c4 * 4) = w;
    }
    #pragma unroll
    for (int j = 0; j < 6; j++) {   // tile 1: sl=1 -> k rows 64.., d-chunk 0
        int idx = j * THREADS + tid;
        int p = idx / 48, c4 = idx % 48;
        const float* s0 = x + (size_t)(segbase + 128 + 4 * p) * DIM + c4 * 4;
        float4 lo = *(const float4*)s0;
        float4 hi = *(const float4*)(s0 + 2 * DIM);
        uint4 w = make_uint4(h2u(lo.x, hi.x), h2u(lo.y, hi.y),
                             h2u(lo.z, hi.z), h2u(lo.w, hi.w));
        *(uint4*)(smu + V_OFFW + VSLABW + p * VSW + c4 * 4) = w;
    }

    // ============ Phase 3: D = P V (128 x 768), flattened (ch,sl), 3-slot V ring ======
    float o[4][6][4];
    #pragma unroll
    for (int mt = 0; mt < 4; mt++)
        #pragma unroll
        for (int nt = 0; nt < 6; nt++)
            #pragma unroll
            for (int i = 0; i < 4; i++)
                o[mt][nt][i] = 0.f;

    for (int t = 0; t < NIT3; t++) {
        __syncthreads();
        const int sl = t & 3;
        const int d0 = (t >> 2) * DCH;
        const bool doSTS = (t >= 1) && (t + 1 < NIT3);
        const bool doLDG = (t + 2 < NIT3);
        uint32_t* stsDst = smu + V_OFFW + ((t + 1) % 3) * VSLABW;
        const int t2sl = (t + 2) & 3;
        const int t2d0 = ((t + 2) >> 2) * DCH;
        const uint32_t* vcur = smu + V_OFFW + (t % 3) * VSLABW;
        const uint32_t* abase = smu + (wm * 64 + ln4) * PSW + sl * 32 + lc4;
        const uint32_t* bbase = vcur + lc4 * VSW + wn * 48 + ln4;

        uint32_t aF[2][4][4], bF[2][2];
        #pragma unroll
        for (int mt = 0; mt < 4; mt++) {
            const uint32_t* ba = abase + mt * 2112;
            aF[0][mt][0] = ba[0];
            aF[0][mt][1] = ba[1056];
            aF[0][mt][2] = ba[4];
            aF[0][mt][3] = ba[1060];
        }
        bF[0][0] = bbase[0];
        bF[0][1] = bbase[800];

        #pragma unroll
        for (int ks = 0; ks < 4; ks++) {
            const int cs = ks & 1;
            #pragma unroll
            for (int nt = 0; nt < 6; nt++) {
                const int cb = nt & 1, nb = cb ^ 1;
                if (nt < 5) {
                    const uint32_t* bb = bbase + ks * 8 * VSW + (nt + 1) * 8;
                    bF[nb][0] = bb[0];
                    bF[nb][1] = bb[800];
                } else if (ks < 3) {
                    const uint32_t* bb = bbase + (ks + 1) * 8 * VSW;
                    bF[nb][0] = bb[0];
                    bF[nb][1] = bb[800];
                }
                if (ks < 3 && nt < 4) {
                    const int mt = nt;
                    const uint32_t* ba = abase + mt * 2112 + (ks + 1) * 8;
                    aF[cs ^ 1][mt][0] = ba[0];
                    aF[cs ^ 1][mt][1] = ba[1056];
                    aF[cs ^ 1][mt][2] = ba[4];
                    aF[cs ^ 1][mt][3] = ba[1060];
                }
                // STS tile t+1 (6 units at ks==0)
                if (ks == 0 && doSTS) {
                    int idx = nt * THREADS + tid;
                    int p = idx / 48, c4 = idx % 48;
                    float4 lo = vstg[2 * nt], hi = vstg[2 * nt + 1];
                    uint4 w = make_uint4(h2u(lo.x, hi.x), h2u(lo.y, hi.y),
                                         h2u(lo.z, hi.z), h2u(lo.w, hi.w));
                    *(uint4*)(stsDst + p * VSW + c4 * 4) = w;
                }
                // LDG tile t+2 (12 loads at ks in {1,2})
                if (doLDG && (ks == 1 || ks == 2)) {
                    const int l = (ks - 1) * 6 + nt;
                    const int u = l >> 1, which = l & 1;
                    int idx = u * THREADS + tid;
                    int p = idx / 48, c4 = idx % 48;
                    const float* s0 = x + (size_t)(segbase + 2 * (t2sl * 64 + 2 * p) + 2 * which) * DIM
                                        + t2d0 + c4 * 4;
                    vstg[2 * u + which] = *(const float4*)s0;
                }
                SCHED_FENCE();
                #pragma unroll
                for (int mt = 0; mt < 4; mt++)
                    mma16(o[mt][nt], aF[cs][mt], bF[cb]);
                SCHED_FENCE();
            }
        }

        if (sl == 3) {
            // Epilogue for this d-chunk: even (gathered) rows get results
            #pragma unroll
            for (int mt = 0; mt < 4; mt++)
                #pragma unroll
                for (int nt = 0; nt < 6; nt++) {
                    int gr = m0 + wm * 64 + mt * 16 + ln4;
                    int c  = d0 + wn * 48 + nt * 8 + 2 * lc4;
                    long tok0 = segbase + 2 * (long)gr;
                    long tok1 = segbase + 2 * (long)(gr + 8);
                    *(float2*)(y + (size_t)tok0 * DIM + c) = make_float2(o[mt][nt][0], o[mt][nt][1]);
                    *(float2*)(y + (size_t)tok1 * DIM + c) = make_float2(o[mt][nt][2], o[mt][nt][3]);
                    #pragma unroll
                    for (int i = 0; i < 4; i++) o[mt][nt][i] = 0.f;
                }
        }
    }
}

extern "C" void kernel_launch(void* const* d_in, const int* in_sizes, int n_in,
                              void* d_out, int out_size)
{
    const float* x = (const float*)d_in[0];
    float* y = (float*)d_out;
    cudaFuncSetAttribute(dilated_attn_kernel,
                         cudaFuncAttributeMaxDynamicSharedMemorySize, SMEM_BYTES);
    dilated_attn_kernel<<<BATCH * NSEG * 2, THREADS, SMEM_BYTES>>>(x, y);
}